// round 9
// baseline (speedup 1.0000x reference)
#include <cuda_runtime.h>

// ---------------------------------------------------------------------------
// QWTForward collapses to: D = bicubic_down2(image); out[q][b] = D * (S_a*S_b)
// where S_* are the sums of the 4 filter tap arrays (reference's filt(x,h)
// is exactly x * sum(h), and downsample is linear).
//
// CRITICAL: sum(gh), sum(fl), sum(fh) are analytically-zero rounding residue;
// outputs 1-3 are proportional to it. Summation must be SEQUENTIAL per filter
// (matches jnp.sum rounding). The unrolled form keeps the add order while
// issuing loads in parallel.
//
// R9 structure: single fused kernel, LATE barrier. Threads 0-15 compute the
// scale factors while ALL warps issue the body's 16 independent loads and
// reduce dval; __syncthreads() only before the store loop, so the prologue
// latency hides under the body's DRAM load latency instead of serializing
// ahead of it (R5's mistake). Removes the 2nd graph node (~3us measured).
// Body is R1's measured-best: 1 px/thread, 16 scalar LDG, 16 coalesced STG.
// ---------------------------------------------------------------------------

__global__ __launch_bounds__(256) void qwt_fused_kernel(
    const float* __restrict__ img,
    const float* __restrict__ gl, const float* __restrict__ gh,
    const float* __restrict__ fl, const float* __restrict__ fh,
    float* __restrict__ out, int NC, int L) {

    __shared__ __align__(16) float sc[16];

    // ---- prologue (warp 0, threads 0-15): sequential-order sums ----
    if (threadIdx.x < 16) {
        const int t = threadIdx.x;
        const int q = t >> 2, b = t & 3;
        const int fi = ((b & 1) << 1) | (q >> 1);
        const int si = ((b >> 1) << 1) | (q & 1);
        const float* Ff = (fi == 0) ? gl : (fi == 1) ? gh : (fi == 2) ? fl : fh;
        const float* Fs = (si == 0) ? gl : (si == 1) ? gh : (si == 2) ? fl : fh;
        float sf = 0.f, ss = 0.f;
        if (L == 30) {
            float a[30], c[30];
#pragma unroll
            for (int i = 0; i < 30; i++) { a[i] = __ldg(Ff + i); c[i] = __ldg(Fs + i); }
#pragma unroll
            for (int i = 0; i < 30; i++) { sf += a[i]; ss += c[i]; }
        } else {
            for (int i = 0; i < L; i++) { sf += Ff[i]; ss += Fs[i]; }
        }
        sc[t] = sf * ss;
    }

    // ---- body: one output pixel of D per thread (independent of sc) ----
    const unsigned idx = blockIdx.x * 256u + threadIdx.x;
    const unsigned x  = idx & 255u;
    const unsigned y  = (idx >> 8) & 255u;
    const unsigned nc = idx >> 16;

    const float* src = img + (size_t)nc * (512u * 512u);

    const int xb = 2 * (int)x - 1;
    const int yb = 2 * (int)y - 1;
    const int x0 = max(xb, 0);
    const int x1 = xb + 1;
    const int x2 = xb + 2;
    const int x3 = min(xb + 3, 511);
    const int y0 = max(yb, 0);
    const int y3 = min(yb + 3, 511);

    const float w0 = -0.09375f;
    const float w1 =  0.59375f;

    const float* r0 = src + (size_t)y0 * 512;
    const float* r1 = src + (size_t)(yb + 1) * 512;
    const float* r2 = src + (size_t)(yb + 2) * 512;
    const float* r3 = src + (size_t)y3 * 512;

    float h0 = w0 * (__ldg(r0 + x0) + __ldg(r0 + x3)) + w1 * (__ldg(r0 + x1) + __ldg(r0 + x2));
    float h1 = w0 * (__ldg(r1 + x0) + __ldg(r1 + x3)) + w1 * (__ldg(r1 + x1) + __ldg(r1 + x2));
    float h2 = w0 * (__ldg(r2 + x0) + __ldg(r2 + x3)) + w1 * (__ldg(r2 + x1) + __ldg(r2 + x2));
    float h3 = w0 * (__ldg(r3 + x0) + __ldg(r3 + x3)) + w1 * (__ldg(r3 + x1) + __ldg(r3 + x2));

    const float dval = w0 * (h0 + h3) + w1 * (h1 + h2);

    // ---- LATE barrier: prologue latency already hidden under body loads ----
    __syncthreads();

    const unsigned n = nc / 3u;
    const unsigned c = nc - 3u * n;
    const size_t plane = 256u * 256u;
    const size_t base  = ((size_t)(n * 12u + c)) * plane + (size_t)y * 256u + x;
    const size_t QS    = (size_t)(NC / 3) * 12u * plane;  // elements per output tensor

    const float4* scv = (const float4*)sc;
#pragma unroll
    for (int q = 0; q < 4; q++) {
        const float4 sv = scv[q];
        float* o = out + base + (size_t)q * QS;
        o[0]         = dval * sv.x;
        o[3 * plane] = dval * sv.y;
        o[6 * plane] = dval * sv.z;
        o[9 * plane] = dval * sv.w;
    }
}

extern "C" void kernel_launch(void* const* d_in, const int* in_sizes, int n_in,
                              void* d_out, int out_size) {
    const float* img = (const float*)d_in[0];
    const float* gl  = (const float*)d_in[1];
    const float* gh  = (const float*)d_in[2];
    const float* fl  = (const float*)d_in[3];
    const float* fh  = (const float*)d_in[4];

    const int L  = in_sizes[1];                 // filter length (30)
    const int NC = in_sizes[0] / (512 * 512);   // N*3 = 48 channels

    const int total_threads = NC * 256 * 256;   // one per downsampled pixel
    qwt_fused_kernel<<<total_threads / 256, 256>>>(img, gl, gh, fl, fh,
                                                   (float*)d_out, NC, L);
}

// round 10
// speedup vs baseline: 1.0702x; 1.0702x over previous
#include <cuda_runtime.h>

// ---------------------------------------------------------------------------
// QWTForward collapses to: D = bicubic_down2(image); out[q][b] = D * (S_a*S_b)
// where S_* are the sums of the 4 filter tap arrays (reference's filt(x,h)
// is exactly x * sum(h), and downsample is linear).
//
// CRITICAL: sum(gh), sum(fl), sum(fh) are analytically-zero rounding residue;
// outputs 1-3 are proportional to it. Summation must be SEQUENTIAL per filter
// (matches jnp.sum rounding). Unrolling keeps the add order while issuing the
// 30 loads in parallel.
//
// R10: single fused kernel, MINIMAL prologue. Threads 0-3 each sum ONE filter
// (120 LDG/block total vs 960 in R9 -> +3% L1 wavefronts instead of +24%,
// which was R9's regression). __syncwarp combines s[4] -> sc[16] inside warp
// 0; the full barrier is LATE (after the body's independent loads+reduce) so
// prologue latency hides under body DRAM latency. Body = R1 measured-best:
// 1 px/thread, 16 scalar LDG, 16 plain coalesced STG.
// ---------------------------------------------------------------------------

__global__ __launch_bounds__(256) void qwt_fused_kernel(
    const float* __restrict__ img,
    const float* __restrict__ gl, const float* __restrict__ gh,
    const float* __restrict__ fl, const float* __restrict__ fh,
    float* __restrict__ out, int NC, int L) {

    __shared__ float s4[4];
    __shared__ __align__(16) float sc[16];

    // ---- prologue: warp 0 only (threads 0-3 load, 0-15 combine) ----
    if (threadIdx.x < 32) {
        const int t = threadIdx.x;
        if (t < 4) {
            const float* F = (t == 0) ? gl : (t == 1) ? gh : (t == 2) ? fl : fh;
            float s = 0.f;
            if (L == 30) {
                float a[30];
#pragma unroll
                for (int i = 0; i < 30; i++) a[i] = __ldg(F + i);
#pragma unroll
                for (int i = 0; i < 30; i++) s += a[i];
            } else {
                for (int i = 0; i < L; i++) s += F[i];
            }
            s4[t] = s;
        }
        __syncwarp();
        if (t < 16) {
            const int q = t >> 2, b = t & 3;
            const int fi = ((b & 1) << 1) | (q >> 1);
            const int si = ((b >> 1) << 1) | (q & 1);
            sc[t] = s4[fi] * s4[si];
        }
    }

    // ---- body: one output pixel of D per thread (independent of sc) ----
    const unsigned idx = blockIdx.x * 256u + threadIdx.x;
    const unsigned x  = idx & 255u;
    const unsigned y  = (idx >> 8) & 255u;
    const unsigned nc = idx >> 16;

    const float* src = img + (size_t)nc * (512u * 512u);

    const int xb = 2 * (int)x - 1;
    const int yb = 2 * (int)y - 1;
    const int x0 = max(xb, 0);
    const int x1 = xb + 1;
    const int x2 = xb + 2;
    const int x3 = min(xb + 3, 511);
    const int y0 = max(yb, 0);
    const int y3 = min(yb + 3, 511);

    const float w0 = -0.09375f;
    const float w1 =  0.59375f;

    const float* r0 = src + (size_t)y0 * 512;
    const float* r1 = src + (size_t)(yb + 1) * 512;
    const float* r2 = src + (size_t)(yb + 2) * 512;
    const float* r3 = src + (size_t)y3 * 512;

    float h0 = w0 * (__ldg(r0 + x0) + __ldg(r0 + x3)) + w1 * (__ldg(r0 + x1) + __ldg(r0 + x2));
    float h1 = w0 * (__ldg(r1 + x0) + __ldg(r1 + x3)) + w1 * (__ldg(r1 + x1) + __ldg(r1 + x2));
    float h2 = w0 * (__ldg(r2 + x0) + __ldg(r2 + x3)) + w1 * (__ldg(r2 + x1) + __ldg(r2 + x2));
    float h3 = w0 * (__ldg(r3 + x0) + __ldg(r3 + x3)) + w1 * (__ldg(r3 + x1) + __ldg(r3 + x2));

    const float dval = w0 * (h0 + h3) + w1 * (h1 + h2);

    // ---- LATE barrier: prologue latency hidden under the body's loads ----
    __syncthreads();

    const unsigned n = nc / 3u;
    const unsigned c = nc - 3u * n;
    const size_t plane = 256u * 256u;
    const size_t base  = ((size_t)(n * 12u + c)) * plane + (size_t)y * 256u + x;
    const size_t QS    = (size_t)(NC / 3) * 12u * plane;  // elements per output tensor

    const float4* scv = (const float4*)sc;
#pragma unroll
    for (int q = 0; q < 4; q++) {
        const float4 sv = scv[q];
        float* o = out + base + (size_t)q * QS;
        o[0]         = dval * sv.x;
        o[3 * plane] = dval * sv.y;
        o[6 * plane] = dval * sv.z;
        o[9 * plane] = dval * sv.w;
    }
}

extern "C" void kernel_launch(void* const* d_in, const int* in_sizes, int n_in,
                              void* d_out, int out_size) {
    const float* img = (const float*)d_in[0];
    const float* gl  = (const float*)d_in[1];
    const float* gh  = (const float*)d_in[2];
    const float* fl  = (const float*)d_in[3];
    const float* fh  = (const float*)d_in[4];

    const int L  = in_sizes[1];                 // filter length (30)
    const int NC = in_sizes[0] / (512 * 512);   // N*3 = 48 channels

    const int total_threads = NC * 256 * 256;   // one per downsampled pixel
    qwt_fused_kernel<<<total_threads / 256, 256>>>(img, gl, gh, fl, fh,
                                                   (float*)d_out, NC, L);
}